// round 10
// baseline (speedup 1.0000x reference)
#include <cuda_runtime.h>
#include <stdint.h>

// Problem constants (fixed by the dataset)
#define NN 50000
#define EE 800000
#define HH 3
#define OO 64
#define FT 192   // HH*OO

// ---------------- scratch (device globals; allocation-free) ----------------
__device__ __align__(16) float g_fs[(size_t)NN * FT];
__device__ __align__(16) float g_fd[(size_t)NN * FT];
__device__ __align__(16) float g_ha[(size_t)NN * FT];
__device__ __align__(16) float g_hb[(size_t)NN * FT];
__device__ int g_deg[NN];
__device__ int g_off[NN + 1];
__device__ int g_cur[NN];
__device__ int g_ss[EE];         // src ids sorted by dst
__device__ __align__(16) float g_pool[128 * OO];
__device__ __align__(16) float g_cnt[128];

__device__ __forceinline__ float lrelu(float x, float s) { return x > 0.f ? x : s * x; }

__device__ __forceinline__ uint32_t rna(uint32_t rawf32) {
    uint32_t u;
    asm("cvt.rna.tf32.f32 %0, %1;" : "=r"(u) : "r"(rawf32));
    return u;
}

// ---------------- CSR construction (counting sort by dst) ----------------
__global__ void hist_kernel(const int* __restrict__ dst, int* __restrict__ deg, int E) {
    int e = blockIdx.x * blockDim.x + threadIdx.x;
    if (e < E) atomicAdd(&deg[dst[e]], 1);
}

__global__ void scan_kernel(const int* __restrict__ deg, int* __restrict__ off,
                            int* __restrict__ cur, int N, int E) {
    __shared__ int ssum[1024];
    int t = threadIdx.x;
    const int CH = (N + 1023) / 1024;
    int a = t * CH;
    int b = a + CH < N ? a + CH : N;
    int s = 0;
    for (int i = a; i < b; i++) s += deg[i];
    ssum[t] = s;
    __syncthreads();
    #pragma unroll
    for (int o = 1; o < 1024; o <<= 1) {
        int v = (t >= o) ? ssum[t - o] : 0;
        __syncthreads();
        ssum[t] += v;
        __syncthreads();
    }
    int base = (t == 0) ? 0 : ssum[t - 1];
    for (int i = a; i < b; i++) {
        off[i] = base; cur[i] = base; base += deg[i];
    }
    if (t == 1023) off[N] = E;
}

__global__ void scatter_kernel(const int* __restrict__ src, const int* __restrict__ dst,
                               int* __restrict__ cur, int* __restrict__ ss, int E) {
    int e = blockIdx.x * blockDim.x + threadIdx.x;
    if (e >= E) return;
    int p = atomicAdd(&cur[dst[e]], 1);
    ss[p] = src[e];
}

// ---------------- TF32 GEMM with cp.async double buffering (R5, measured) ----
#define GBM 128
#define GBN 64
#define GBK 32
#define AROW 36    // 36 % 32 == 4 -> fragment bank 4*gid+tig unique
#define BROW 72    // 72 % 32 == 8 -> fragment bank 8*tig+gid unique

__device__ __forceinline__ void cpa16(uint32_t dst, const void* src) {
    asm volatile("cp.async.cg.shared.global [%0], [%1], 16;" :: "r"(dst), "l"(src));
}

__global__ __launch_bounds__(256) void gemm_tf32(
    const float* __restrict__ A, const float* __restrict__ W,
    const float* __restrict__ bias, float* __restrict__ C,
    int M, int K, int Nc)
{
    extern __shared__ uint32_t sh[];
    uint32_t* As = sh;                          // [2][GBM][AROW]
    uint32_t* Bs = sh + 2 * GBM * AROW;         // [2][GBK][BROW]

    const int tid  = threadIdx.x;
    const int wid  = tid >> 5;
    const int lane = tid & 31;
    const int warpM = wid >> 1;
    const int warpN = wid & 1;
    const int gid = lane >> 2;
    const int tig = lane & 3;
    const int row0 = blockIdx.y * GBM;
    const int col0 = blockIdx.x * GBN;

    const int nch = K / GBK;
    float c[2][4][4] = {};

    #define STAGE(ch, buf) do {                                                   \
        int k0_ = (ch) * GBK;                                                     \
        _Pragma("unroll")                                                         \
        for (int i = 0; i < 4; i++) {                                             \
            int cc = tid + 256 * i;                    /* 0..1023 */              \
            int r  = cc >> 3;                          /* 0..127 */               \
            int kc = (cc & 7) << 2;                    /* 0,4..28 */              \
            uint32_t* dp = As + ((buf) * GBM + r) * AROW + kc;                    \
            if (row0 + r < M)                                                     \
                cpa16((uint32_t)__cvta_generic_to_shared(dp),                     \
                      A + (size_t)(row0 + r) * K + k0_ + kc);                     \
            else                                                                  \
                *(uint4*)dp = make_uint4(0u, 0u, 0u, 0u);                         \
        }                                                                         \
        _Pragma("unroll")                                                         \
        for (int i = 0; i < 2; i++) {                                             \
            int cc = tid + 256 * i;                    /* 0..511 */               \
            int r  = cc >> 4;                          /* 0..31 */                \
            int nc = (cc & 15) << 2;                   /* 0..60 */                \
            uint32_t* dp = Bs + ((buf) * GBK + r) * BROW + nc;                    \
            cpa16((uint32_t)__cvta_generic_to_shared(dp),                         \
                  W + (size_t)(k0_ + r) * Nc + col0 + nc);                        \
        }                                                                         \
        asm volatile("cp.async.commit_group;");                                   \
    } while (0)

    STAGE(0, 0);

    for (int ch = 0; ch < nch; ch++) {
        int buf = ch & 1;
        if (ch + 1 < nch) {
            STAGE(ch + 1, buf ^ 1);
            asm volatile("cp.async.wait_group 1;");
        } else {
            asm volatile("cp.async.wait_group 0;");
        }
        __syncthreads();

        const uint32_t* Ab = As + buf * GBM * AROW;
        const uint32_t* Bb = Bs + buf * GBK * BROW;

        #pragma unroll
        for (int ks = 0; ks < 4; ks++) {
            const int kk = ks * 8;
            uint32_t a[2][4], b[4][2];
            #pragma unroll
            for (int mi = 0; mi < 2; mi++) {
                int rb = warpM * 32 + mi * 16;
                a[mi][0] = rna(Ab[(rb + gid) * AROW + kk + tig]);
                a[mi][1] = rna(Ab[(rb + gid + 8) * AROW + kk + tig]);
                a[mi][2] = rna(Ab[(rb + gid) * AROW + kk + tig + 4]);
                a[mi][3] = rna(Ab[(rb + gid + 8) * AROW + kk + tig + 4]);
            }
            #pragma unroll
            for (int ni = 0; ni < 4; ni++) {
                int cb = warpN * 32 + ni * 8;
                b[ni][0] = rna(Bb[(kk + tig) * BROW + cb + gid]);
                b[ni][1] = rna(Bb[(kk + tig + 4) * BROW + cb + gid]);
            }
            #pragma unroll
            for (int mi = 0; mi < 2; mi++)
                #pragma unroll
                for (int ni = 0; ni < 4; ni++)
                    asm volatile(
                        "mma.sync.aligned.m16n8k8.row.col.f32.tf32.tf32.f32 "
                        "{%0,%1,%2,%3}, {%4,%5,%6,%7}, {%8,%9}, {%0,%1,%2,%3};"
                        : "+f"(c[mi][ni][0]), "+f"(c[mi][ni][1]),
                          "+f"(c[mi][ni][2]), "+f"(c[mi][ni][3])
                        : "r"(a[mi][0]), "r"(a[mi][1]), "r"(a[mi][2]), "r"(a[mi][3]),
                          "r"(b[ni][0]), "r"(b[ni][1]));
        }
        __syncthreads();
    }
    #undef STAGE

    #pragma unroll
    for (int mi = 0; mi < 2; mi++) {
        #pragma unroll
        for (int ni = 0; ni < 4; ni++) {
            int gcol = col0 + warpN * 32 + ni * 8 + tig * 2;
            float bx = bias[gcol], by = bias[gcol + 1];
            int r0 = row0 + warpM * 32 + mi * 16 + gid;
            if (r0 < M) {
                float2 o = make_float2(c[mi][ni][0] + bx, c[mi][ni][1] + by);
                *(float2*)(C + (size_t)r0 * Nc + gcol) = o;
            }
            int r1 = r0 + 8;
            if (r1 < M) {
                float2 o = make_float2(c[mi][ni][2] + bx, c[mi][ni][3] + by);
                *(float2*)(C + (size_t)r1 * Nc + gcol) = o;
            }
        }
    }
}

// ---------------- fused GATv2: one warp per (node, head) ----------------------
// 8 lanes per edge (lane sl owns elems 8*sl..8*sl+7 of the 64-dim head),
// 4 edges per iteration (sub = lane>>3). 3-level butterfly, 2 exp per iter.
// Four sub-states merged at the end via 2 shuffle rounds.
__global__ __launch_bounds__(256) void gat_head_kernel(
    const float* __restrict__ fs, const float* __restrict__ fd,
    const int* __restrict__ off, const int* __restrict__ ss,
    const float* __restrict__ attn, float* __restrict__ hout, int N)
{
    __shared__ float sattn[FT];
    if (threadIdx.x < FT) sattn[threadIdx.x] = attn[threadIdx.x];
    __syncthreads();

    int wg = blockIdx.x * 8 + (threadIdx.x >> 5);
    if (wg >= N * 3) return;
    int node = wg / 3;
    int head = wg - node * 3;
    int lane = threadIdx.x & 31;
    int sub  = lane >> 3;     // edge slot 0..3
    int sl   = lane & 7;      // element lane within edge
    int e0 = off[node], e1 = off[node + 1];

    float* po = hout + (size_t)node * FT + head * 64 + 8 * sl;

    if (e0 >= e1) {  // degree-0 node: zeros
        if (sub == 0) {
            float4 z = make_float4(0.f, 0.f, 0.f, 0.f);
            *(float4*)(po) = z; *(float4*)(po + 4) = z;
        }
        return;
    }

    const float* fdp = fd + (size_t)node * FT + head * 64 + 8 * sl;
    float4 fd0 = *(const float4*)(fdp);
    float4 fd1 = *(const float4*)(fdp + 4);
    float4 a0  = *(const float4*)(sattn + head * 64 + 8 * sl);
    float4 a1  = *(const float4*)(sattn + head * 64 + 8 * sl + 4);

    float m = -3.0e38f, den = 0.f;
    float4 ac0 = make_float4(0.f, 0.f, 0.f, 0.f);
    float4 ac1 = ac0;

    const float* fsb = fs + head * 64 + 8 * sl;

    for (int p = e0; p < e1; p += 4) {
        int q = p + sub;
        bool valid = (q < e1);
        int s = ss[valid ? q : e1 - 1];
        const float* fp = fsb + (size_t)s * FT;
        float4 p0 = *(const float4*)(fp);
        float4 p1 = *(const float4*)(fp + 4);

        float t = lrelu(p0.x + fd0.x, 0.2f) * a0.x + lrelu(p0.y + fd0.y, 0.2f) * a0.y
                + lrelu(p0.z + fd0.z, 0.2f) * a0.z + lrelu(p0.w + fd0.w, 0.2f) * a0.w
                + lrelu(p1.x + fd1.x, 0.2f) * a1.x + lrelu(p1.y + fd1.y, 0.2f) * a1.y
                + lrelu(p1.z + fd1.z, 0.2f) * a1.z + lrelu(p1.w + fd1.w, 0.2f) * a1.w;

        // 3-level butterfly within each 8-lane group
        t += __shfl_xor_sync(0xffffffffu, t, 1);
        t += __shfl_xor_sync(0xffffffffu, t, 2);
        t += __shfl_xor_sync(0xffffffffu, t, 4);

        float nm = fmaxf(m, t);
        float sc = __expf(m - nm);
        float w  = __expf(t - nm);
        if (!valid) w = 0.f;
        m = nm;
        den = den * sc + w;
        ac0.x = fmaf(ac0.x, sc, w * p0.x); ac0.y = fmaf(ac0.y, sc, w * p0.y);
        ac0.z = fmaf(ac0.z, sc, w * p0.z); ac0.w = fmaf(ac0.w, sc, w * p0.w);
        ac1.x = fmaf(ac1.x, sc, w * p1.x); ac1.y = fmaf(ac1.y, sc, w * p1.y);
        ac1.z = fmaf(ac1.z, sc, w * p1.z); ac1.w = fmaf(ac1.w, sc, w * p1.w);
    }

    // ---- merge the 4 sub-states (element ownership aligns on sl) ----
    #pragma unroll
    for (int o = 8; o <= 16; o <<= 1) {
        float mo = __shfl_xor_sync(0xffffffffu, m, o);
        float nm = fmaxf(m, mo);
        float sc = __expf(m - nm);
        m = nm;
        den *= sc;
        ac0.x *= sc; ac0.y *= sc; ac0.z *= sc; ac0.w *= sc;
        ac1.x *= sc; ac1.y *= sc; ac1.z *= sc; ac1.w *= sc;
        den += __shfl_xor_sync(0xffffffffu, den, o);
        ac0.x += __shfl_xor_sync(0xffffffffu, ac0.x, o);
        ac0.y += __shfl_xor_sync(0xffffffffu, ac0.y, o);
        ac0.z += __shfl_xor_sync(0xffffffffu, ac0.z, o);
        ac0.w += __shfl_xor_sync(0xffffffffu, ac0.w, o);
        ac1.x += __shfl_xor_sync(0xffffffffu, ac1.x, o);
        ac1.y += __shfl_xor_sync(0xffffffffu, ac1.y, o);
        ac1.z += __shfl_xor_sync(0xffffffffu, ac1.z, o);
        ac1.w += __shfl_xor_sync(0xffffffffu, ac1.w, o);
    }

    if (sub == 0) {
        float r = 1.f / fmaxf(den, 1e-9f);
        *(float4*)(po)     = make_float4(ac0.x * r, ac0.y * r, ac0.z * r, ac0.w * r);
        *(float4*)(po + 4) = make_float4(ac1.x * r, ac1.y * r, ac1.z * r, ac1.w * r);
    }
}

// ---------------- head-mean + per-graph pooling ----------------
__global__ void pool_kernel(const float* __restrict__ h, const int* __restrict__ gid,
                            float* __restrict__ pool, float* __restrict__ cnt, int N) {
    int idx = blockIdx.x * blockDim.x + threadIdx.x;
    if (idx >= N * OO) return;
    int n = idx >> 6, k = idx & 63;
    const float* p = h + (size_t)n * FT;
    float v = (p[k] + p[64 + k] + p[128 + k]) * (1.0f / 3.0f);
    int g = gid[n];
    atomicAdd(&pool[g * OO + k], v);
    if (k == 0) atomicAdd(&cnt[g], 1.0f);
}

// ---------------- final MLP: 64 -> 64 -> 32 -> 2, leaky 0.01 ----------------
__global__ void mlp_kernel(const float* __restrict__ pool, const float* __restrict__ cnt,
                           const float* __restrict__ W1, const float* __restrict__ b1,
                           const float* __restrict__ W2, const float* __restrict__ b2,
                           const float* __restrict__ W3, const float* __restrict__ b3,
                           float* __restrict__ out) {
    int g = blockIdx.x;
    int j = threadIdx.x;  // 64 threads
    __shared__ float gv[64], t1[64], t2[32];
    float c = fmaxf(cnt[g], 1.0f);
    gv[j] = pool[g * OO + j] / c;
    __syncthreads();
    float a = b1[j];
    #pragma unroll 8
    for (int k = 0; k < 64; k++) a = fmaf(gv[k], W1[k * 64 + j], a);
    t1[j] = lrelu(a, 0.01f);
    __syncthreads();
    if (j < 32) {
        float a2 = b2[j];
        #pragma unroll 8
        for (int k = 0; k < 64; k++) a2 = fmaf(t1[k], W2[k * 32 + j], a2);
        t2[j] = lrelu(a2, 0.01f);
    }
    __syncthreads();
    if (j < 2) {
        float a3 = b3[j];
        #pragma unroll
        for (int k = 0; k < 32; k++) a3 = fmaf(t2[k], W3[k * 2 + j], a3);
        out[g * 2 + j] = lrelu(a3, 0.01f);
    }
}

// ---------------- launcher ----------------
extern "C" void kernel_launch(void* const* d_in, const int* in_sizes, int n_in,
                              void* d_out, int out_size) {
    const float* x   = (const float*)d_in[0];
    const int*   src = (const int*)d_in[1];
    const int*   dst = (const int*)d_in[2];
    const int*   gid = (const int*)d_in[3];
    const float* Wsrc[3] = {(const float*)d_in[5],  (const float*)d_in[10], (const float*)d_in[15]};
    const float* bsrc[3] = {(const float*)d_in[6],  (const float*)d_in[11], (const float*)d_in[16]};
    const float* Wdst[3] = {(const float*)d_in[7],  (const float*)d_in[12], (const float*)d_in[17]};
    const float* bdst[3] = {(const float*)d_in[8],  (const float*)d_in[13], (const float*)d_in[18]};
    const float* attn[3] = {(const float*)d_in[9],  (const float*)d_in[14], (const float*)d_in[19]};
    const float* W1 = (const float*)d_in[20];
    const float* b1 = (const float*)d_in[21];
    const float* W2 = (const float*)d_in[22];
    const float* b2 = (const float*)d_in[23];
    const float* W3 = (const float*)d_in[24];
    const float* b3 = (const float*)d_in[25];

    const int N  = in_sizes[0] / 128;
    const int E  = in_sizes[1];
    const int ng = out_size / 2;

    float *fs, *fd, *ha, *hb, *pool, *cnt;
    int *deg, *off, *cur, *ssorted;
    cudaGetSymbolAddress((void**)&fs,   g_fs);
    cudaGetSymbolAddress((void**)&fd,   g_fd);
    cudaGetSymbolAddress((void**)&ha,   g_ha);
    cudaGetSymbolAddress((void**)&hb,   g_hb);
    cudaGetSymbolAddress((void**)&deg,  g_deg);
    cudaGetSymbolAddress((void**)&off,  g_off);
    cudaGetSymbolAddress((void**)&cur,  g_cur);
    cudaGetSymbolAddress((void**)&ssorted, g_ss);
    cudaGetSymbolAddress((void**)&pool, g_pool);
    cudaGetSymbolAddress((void**)&cnt,  g_cnt);

    // GEMM dynamic smem (55296 B > 48 KB static limit)
    const int GEMM_SMEM = (2 * GBM * AROW + 2 * GBK * BROW) * 4;
    cudaFuncSetAttribute(gemm_tf32, cudaFuncAttributeMaxDynamicSharedMemorySize, GEMM_SMEM);

    // ---- CSR build (once; reused by all 3 layers)
    cudaMemsetAsync(deg, 0, (size_t)N * sizeof(int), 0);
    hist_kernel<<<(E + 255) / 256, 256>>>(dst, deg, E);
    scan_kernel<<<1, 1024>>>(deg, off, cur, N, E);
    scatter_kernel<<<(E + 255) / 256, 256>>>(src, dst, cur, ssorted, E);

    const float* hin = x;
    int Fin = 128;
    float* houts[3] = {ha, hb, ha};
    const int headBlocks = (N * 3 + 7) / 8;   // one warp per (node, head)

    for (int l = 0; l < 3; l++) {
        dim3 gg(FT / GBN, (N + GBM - 1) / GBM);
        gemm_tf32<<<gg, 256, GEMM_SMEM>>>(hin, Wsrc[l], bsrc[l], fs, N, Fin, FT);
        gemm_tf32<<<gg, 256, GEMM_SMEM>>>(hin, Wdst[l], bdst[l], fd, N, Fin, FT);
        gat_head_kernel<<<headBlocks, 256>>>(fs, fd, off, ssorted, attn[l], houts[l], N);
        hin = houts[l];
        Fin = FT;
    }

    cudaMemsetAsync(pool, 0, 128 * OO * sizeof(float), 0);
    cudaMemsetAsync(cnt,  0, 128 * sizeof(float), 0);
    pool_kernel<<<(N * OO + 255) / 256, 256>>>(hin, gid, pool, cnt, N);
    mlp_kernel<<<ng, 64>>>(pool, cnt, W1, b1, W2, b2, W3, b3, (float*)d_out);
}